// round 16
// baseline (speedup 1.0000x reference)
#include <cuda_runtime.h>
#include <cuda_fp16.h>
#include <math.h>

#define B_TOTAL 131072
#define KNB 5
#define TILE_B 32
#define ROWSF (TILE_B * KNB)   // 160
#define HID 256
#define AH 128
#define HLD 272                // hbar stride (16 mod 32 -> conflict-free LDS.128)
#define NRES 21
#define NSS 9
#define NRS (NRES * NSS)       // 189

typedef unsigned int uint32;

// ---------------- device globals ----------------
__device__ float g_R1a[NRES * AH];
__device__ float g_S1a[NSS * AH];
__device__ float g_C1a[6 * AH];
__device__ float g_R1v[NRES * HID];
__device__ float g_S1v[NSS * HID];
__device__ float g_C1v[6 * HID];
__device__ __half g_RS1aH[NRS * AH];   // fused res+ss attn table, fp16 (48 KB)
__device__ __half g_RS1vH[NRS * HID];  // fused res+ss value table, fp16 (97 KB)
__device__ uint32 g_w2T[HID * HID];    // val_W2^T tf32, k16-permuted
__device__ int g_flag_u8, g_flag_f32;

// ---------------- helpers ----------------
__device__ __forceinline__ uint32 f2tf(float f) {
    uint32 r; asm("cvt.rna.tf32.f32 %0, %1;" : "=r"(r) : "f"(f)); return r;
}
__device__ __forceinline__ void mma_tf32(float d[4], uint32 a0, uint32 a1, uint32 a2, uint32 a3,
                                         uint32 b0, uint32 b1) {
    asm("mma.sync.aligned.m16n8k8.row.col.f32.tf32.tf32.f32 "
        "{%0,%1,%2,%3}, {%4,%5,%6,%7}, {%8,%9}, {%0,%1,%2,%3};"
        : "+f"(d[0]), "+f"(d[1]), "+f"(d[2]), "+f"(d[3])
        : "r"(a0), "r"(a1), "r"(a2), "r"(a3), "r"(b0), "r"(b1));
}
// fast GELU via MUFU.TANH
__device__ __forceinline__ float gelu_fast(float x) {
    float s = x * x;
    float t = fmaf(s, 0.0356774081f, 0.7978845608f);
    float u = x * t;
    float th;
    asm("tanh.approx.f32 %0, %1;" : "=f"(th) : "f"(u));
    float h = 0.5f * x;
    return fmaf(h, th, h);
}
// 16-wide k permutation: k = c*8 + h*4 + t  ->  slot = 4t + 2c + h
__device__ __forceinline__ int kperm16(int k) {
    return (k & ~15) | ((k & 3) << 2) | ((k & 8) >> 2) | ((k & 4) >> 2);
}

// ---------------- prep 1: factor tables + W2 transpose ----------------
__global__ void prep_tables(const float* __restrict__ attn_W1,
                            const float* __restrict__ attn_b1,
                            const float* __restrict__ val_W1,
                            const float* __restrict__ val_b1,
                            const float* __restrict__ val_W2,
                            const float* __restrict__ res_table,
                            const float* __restrict__ ss_table,
                            const float* __restrict__ cont_W,
                            const float* __restrict__ cont_b) {
    int tid = blockIdx.x * blockDim.x + threadIdx.x;
    int stride = gridDim.x * blockDim.x;
    for (int i = tid; i < NRES * AH; i += stride) {
        int r = i / AH, n = i % AH;
        float s = attn_b1[n];
        for (int c = 0; c < 64; c++) s += res_table[r * 64 + c] * attn_W1[c * AH + n];
        for (int c = 0; c < 32; c++) s += cont_b[c] * attn_W1[(96 + c) * AH + n];
        g_R1a[i] = s;
    }
    for (int i = tid; i < NSS * AH; i += stride) {
        int r = i / AH, n = i % AH;
        float s = 0.0f;
        for (int c = 0; c < 32; c++) s += ss_table[r * 32 + c] * attn_W1[(64 + c) * AH + n];
        g_S1a[i] = s;
    }
    for (int i = tid; i < 6 * AH; i += stride) {
        int j = i / AH, n = i % AH;
        float s = 0.0f;
        for (int c = 0; c < 32; c++) s += cont_W[j * 32 + c] * attn_W1[(96 + c) * AH + n];
        g_C1a[i] = s;
    }
    for (int i = tid; i < NRES * HID; i += stride) {
        int r = i / HID, n = i % HID;
        float s = val_b1[n];
        for (int c = 0; c < 64; c++) s += res_table[r * 64 + c] * val_W1[c * HID + n];
        for (int c = 0; c < 32; c++) s += cont_b[c] * val_W1[(96 + c) * HID + n];
        g_R1v[i] = s;
    }
    for (int i = tid; i < NSS * HID; i += stride) {
        int r = i / HID, n = i % HID;
        float s = 0.0f;
        for (int c = 0; c < 32; c++) s += ss_table[r * 32 + c] * val_W1[(64 + c) * HID + n];
        g_S1v[i] = s;
    }
    for (int i = tid; i < 6 * HID; i += stride) {
        int j = i / HID, n = i % HID;
        float s = 0.0f;
        for (int c = 0; c < 32; c++) s += cont_W[j * 32 + c] * val_W1[(96 + c) * HID + n];
        g_C1v[i] = s;
    }
    for (int i = tid; i < HID * HID; i += stride) {
        int n = i >> 8, k = i & 255;
        g_w2T[(n << 8) + kperm16(k)] = f2tf(val_W2[k * HID + n]);
    }
}

// ---------------- prep 2: fuse res+ss tables to fp16 ----------------
__global__ void prep_fuse() {
    int tid = blockIdx.x * blockDim.x + threadIdx.x;
    int stride = gridDim.x * blockDim.x;
    for (int i = tid; i < NRS * AH; i += stride) {
        int rs = i / AH, n = i % AH;
        g_RS1aH[i] = __float2half(g_R1a[(rs / NSS) * AH + n] + g_S1a[(rs % NSS) * AH + n]);
    }
    for (int i = tid; i < NRS * HID; i += stride) {
        int rs = i / HID, n = i % HID;
        g_RS1vH[i] = __float2half(g_R1v[(rs / NSS) * HID + n] + g_S1v[(rs % NSS) * HID + n]);
    }
}

// ---------------- valid-dtype probe ----------------
__global__ void reset_flags() { g_flag_u8 = 0; g_flag_f32 = 0; }

__global__ void detect_valid(const unsigned int* __restrict__ v, int n) {
    int f8 = 0, f32 = 0;
    for (int i = blockIdx.x * blockDim.x + threadIdx.x; i < n; i += gridDim.x * blockDim.x) {
        unsigned int w = v[i];
        if (w == 0x3F800000u) f32 = 1;
        else if (w > 1u) f8 = 1;
    }
    if (__syncthreads_or(f8) && threadIdx.x == 0) atomicOr(&g_flag_u8, 1);
    if (__syncthreads_or(f32) && threadIdx.x == 0) atomicOr(&g_flag_f32, 1);
}

// ---------------- fused kernel smem (floats) ----------------
// feat @0: 960 | score @960: 160 | wgt @1120: 160 | hbar @1280: 32*272=8704
// b2s @9984: 256 | fbs @10240: 256 | cidx @10496: 160 | anyv @10656: 32
// total 10688 floats = 42752 B  (3 CTAs/SM = 128 KB)
#define SMEM_BYTES 42752

__global__ void __launch_bounds__(256, 3) fused_all(
    const int* __restrict__ res_idx,
    const int* __restrict__ ss_idx,
    const float* __restrict__ dist,
    const int* __restrict__ seq_sep,
    const float* __restrict__ angles,
    const void* __restrict__ validp,
    const float* __restrict__ attn_W2,
    const float* __restrict__ attn_b2,
    const float* __restrict__ val_b2,
    const float* __restrict__ fallback,
    float* __restrict__ out)
{
    extern __shared__ float sm[];
    float* feat    = sm;
    float* score_s = sm + 960;
    float* wgt_s   = sm + 1120;
    float* hbar_s  = sm + 1280;
    float* b2s     = sm + 9984;
    float* fbs     = sm + 10240;
    int*   cidx    = (int*)(sm + 10496);
    int*   anyv_s  = (int*)(sm + 10656);

    const int tid  = threadIdx.x;
    const int lane = tid & 31;
    const int warp = tid >> 5;      // 0..7
    const int g    = lane >> 2;     // 0..7
    const int t    = lane & 3;      // 0..3
    const int b0   = blockIdx.x * TILE_B;
    const int gr0  = b0 * KNB;

    const uint2*  RS1a2 = (const uint2*)g_RS1aH;   // 32 uint2 per row (128 halves)
    const float4* C1a4  = (const float4*)g_C1a;
    const uint4*  RS1v4 = (const uint4*)g_RS1vH;   // 32 uint4 per row (256 halves)
    const float4* C1v4  = (const float4*)g_C1v;
    const uint32* hbU   = (const uint32*)hbar_s;
    const uint4*  w24   = (const uint4*)g_w2T;     // 64 uint4 per row

    // ---------- phase 0: constants + features + combined idx ----------
    if (tid < HID) { b2s[tid] = val_b2[tid]; fbs[tid] = fallback[tid]; }
    if (tid < ROWSF) {
        int gr = gr0 + tid;
        cidx[tid] = res_idx[gr] * NSS + ss_idx[gr];
        float d = dist[gr];
        if (d != d) d = 0.0f;
        feat[tid * 6 + 0] = d * (1.0f / 15.0f);
        feat[tid * 6 + 1] = log1pf(fabsf((float)seq_sep[gr])) * 0.2f;
        float4 a = ((const float4*)angles)[gr];
        feat[tid * 6 + 2] = (a.x != a.x) ? 0.0f : a.x;
        feat[tid * 6 + 3] = (a.y != a.y) ? 0.0f : a.y;
        feat[tid * 6 + 4] = (a.z != a.z) ? 0.0f : a.z;
        feat[tid * 6 + 5] = (a.w != a.w) ? 0.0f : a.w;
    }
    __syncthreads();

    // ---------- phase 1: attention scores (fp16 table, 1 ldg.64/row/lane) ----------
    {
        float4 c1[6];
        #pragma unroll
        for (int j = 0; j < 6; j++) c1[j] = __ldg(C1a4 + j * 32 + lane);
        float4 w2q = __ldg(((const float4*)attn_W2) + lane);
        #pragma unroll 4
        for (int i = 0; i < 20; i++) {
            int j = warp * 20 + i;
            uint2 pv = __ldg(RS1a2 + cidx[j] * 32 + lane);
            float2 lo = __half22float2(*(const __half2*)&pv.x);
            float2 hi = __half22float2(*(const __half2*)&pv.y);
            float px = lo.x, py = lo.y, pz = hi.x, pw = hi.y;
            const float* fj = feat + j * 6;
            #pragma unroll
            for (int jj = 0; jj < 6; jj++) {
                float f = fj[jj];
                px += f * c1[jj].x; py += f * c1[jj].y;
                pz += f * c1[jj].z; pw += f * c1[jj].w;
            }
            float part = gelu_fast(px) * w2q.x + gelu_fast(py) * w2q.y
                       + gelu_fast(pz) * w2q.z + gelu_fast(pw) * w2q.w;
            #pragma unroll
            for (int off = 16; off; off >>= 1)
                part += __shfl_xor_sync(0xFFFFFFFFu, part, off);
            if (lane == 0) score_s[j] = part;
        }
    }
    __syncthreads();

    // ---------- phase 2: softmax + validity (tid<32) ----------
    if (tid < TILE_B) {
        int gb = b0 + tid;
        float ab2 = attn_b2[0];
        int fu8 = g_flag_u8, ff32 = g_flag_f32;
        float s[KNB];
        int any = 0;
        #pragma unroll
        for (int k = 0; k < KNB; k++) {
            int idx = gb * KNB + k;
            int v;
            if (ff32)      v = (((const float*)validp)[idx] != 0.0f);
            else if (fu8)  v = (((const unsigned char*)validp)[idx] != 0);
            else           v = (((const int*)validp)[idx] != 0);
            any |= v;
            s[k] = v ? (score_s[tid * KNB + k] + ab2) : -10000.0f;
        }
        float m = s[0];
        #pragma unroll
        for (int k = 1; k < KNB; k++) m = fmaxf(m, s[k]);
        float e[KNB], sum = 0.0f;
        #pragma unroll
        for (int k = 0; k < KNB; k++) { e[k] = expf(s[k] - m); sum += e[k]; }
        float inv = 1.0f / sum;
        #pragma unroll
        for (int k = 0; k < KNB; k++) wgt_s[tid * KNB + k] = e[k] * inv;
        anyv_s[tid] = any;
    }
    __syncthreads();

    // ---------- phase 3: value path -> hbar (fp16 table, 8 cols/item) ----------
    // q8 = tid&31 (col group of 8: cols q8*8..q8*8+7); b = tid>>5 + 8*i, i<4
    {
        const int q8 = tid & 31;
        float4 c1lo[6], c1hi[6];
        #pragma unroll
        for (int j = 0; j < 6; j++) {
            c1lo[j] = __ldg(C1v4 + j * 64 + q8 * 2);
            c1hi[j] = __ldg(C1v4 + j * 64 + q8 * 2 + 1);
        }
        #pragma unroll 1
        for (int i = 0; i < 4; i++) {
            int b = (tid >> 5) + 8 * i;
            float a0 = 0.f, a1 = 0.f, a2 = 0.f, a3 = 0.f;
            float a4 = 0.f, a5 = 0.f, a6 = 0.f, a7 = 0.f;
            #pragma unroll
            for (int k = 0; k < KNB; k++) {
                int j = b * KNB + k;
                float wk = wgt_s[j];
                uint4 pv = __ldg(RS1v4 + cidx[j] * 32 + q8);
                float2 f0 = __half22float2(*(const __half2*)&pv.x);
                float2 f1 = __half22float2(*(const __half2*)&pv.y);
                float2 f2 = __half22float2(*(const __half2*)&pv.z);
                float2 f3 = __half22float2(*(const __half2*)&pv.w);
                float p0 = f0.x, p1 = f0.y, p2 = f1.x, p3 = f1.y;
                float p4 = f2.x, p5 = f2.y, p6 = f3.x, p7 = f3.y;
                const float* fj = feat + j * 6;
                #pragma unroll
                for (int jj = 0; jj < 6; jj++) {
                    float f = fj[jj];
                    p0 += f * c1lo[jj].x; p1 += f * c1lo[jj].y;
                    p2 += f * c1lo[jj].z; p3 += f * c1lo[jj].w;
                    p4 += f * c1hi[jj].x; p5 += f * c1hi[jj].y;
                    p6 += f * c1hi[jj].z; p7 += f * c1hi[jj].w;
                }
                a0 += wk * gelu_fast(p0); a1 += wk * gelu_fast(p1);
                a2 += wk * gelu_fast(p2); a3 += wk * gelu_fast(p3);
                a4 += wk * gelu_fast(p4); a5 += wk * gelu_fast(p5);
                a6 += wk * gelu_fast(p6); a7 += wk * gelu_fast(p7);
            }
            int col = q8 * 8;
            float* hb = hbar_s + b * HLD;
            hb[kperm16(col)]     = __uint_as_float(f2tf(a0));
            hb[kperm16(col + 1)] = __uint_as_float(f2tf(a1));
            hb[kperm16(col + 2)] = __uint_as_float(f2tf(a2));
            hb[kperm16(col + 3)] = __uint_as_float(f2tf(a3));
            hb[kperm16(col + 4)] = __uint_as_float(f2tf(a4));
            hb[kperm16(col + 5)] = __uint_as_float(f2tf(a5));
            hb[kperm16(col + 6)] = __uint_as_float(f2tf(a6));
            hb[kperm16(col + 7)] = __uint_as_float(f2tf(a7));
        }
    }
    __syncthreads();

    // ---------- phase 4: output GEMM (32 x 256) @ (256 x 256), tensor cores ----------
    {
        const int nb2 = warp * 32;
        float acc[2][4][4];
        #pragma unroll
        for (int mi = 0; mi < 2; mi++)
            #pragma unroll
            for (int ni = 0; ni < 4; ni++)
                #pragma unroll
                for (int q = 0; q < 4; q++) acc[mi][ni][q] = 0.0f;

        #pragma unroll 2
        for (int ks = 0; ks < 16; ks++) {
            int kb = ks * 16;
            uint4 a0[2], a1[2];
            #pragma unroll
            for (int mi = 0; mi < 2; mi++) {
                const uint32* abase = hbU + (mi * 16 + g) * HLD + kb + 4 * t;
                a0[mi] = *(const uint4*)abase;
                a1[mi] = *(const uint4*)(abase + 8 * HLD);
            }
            #pragma unroll
            for (int ni = 0; ni < 4; ni++) {
                uint4 pb = __ldg(w24 + (nb2 + ni * 8 + g) * 64 + ks * 4 + t);
                #pragma unroll
                for (int mi = 0; mi < 2; mi++) {
                    mma_tf32(acc[mi][ni], a0[mi].x, a1[mi].x, a0[mi].y, a1[mi].y, pb.x, pb.y);
                    mma_tf32(acc[mi][ni], a0[mi].z, a1[mi].z, a0[mi].w, a1[mi].w, pb.z, pb.w);
                }
            }
        }

        #pragma unroll
        for (int mi = 0; mi < 2; mi++) {
            #pragma unroll
            for (int rh = 0; rh < 2; rh++) {
                int b = mi * 16 + g + 8 * rh;
                int av = anyv_s[b];
                int row = b0 + b;
                #pragma unroll
                for (int ni = 0; ni < 4; ni++) {
                    int colb = nb2 + ni * 8 + 2 * t;
                    float x0 = acc[mi][ni][rh * 2 + 0];
                    float x1 = acc[mi][ni][rh * 2 + 1];
                    float2 o;
                    if (av) { o.x = x0 + b2s[colb]; o.y = x1 + b2s[colb + 1]; }
                    else    { o.x = fbs[colb];      o.y = fbs[colb + 1]; }
                    *(float2*)(out + (size_t)row * HID + colb) = o;
                }
            }
        }
    }
}

// ---------------- launch ----------------
extern "C" void kernel_launch(void* const* d_in, const int* in_sizes, int n_in,
                              void* d_out, int out_size)
{
    const int*   res_idx   = (const int*)d_in[0];
    const int*   ss_idx    = (const int*)d_in[1];
    const float* dist      = (const float*)d_in[2];
    const int*   seq_sep   = (const int*)d_in[3];
    const float* angles    = (const float*)d_in[4];
    const void*  validp    = d_in[5];
    const float* res_table = (const float*)d_in[6];
    const float* ss_table  = (const float*)d_in[7];
    const float* cont_W    = (const float*)d_in[8];
    const float* cont_b    = (const float*)d_in[9];
    const float* attn_W1   = (const float*)d_in[10];
    const float* attn_b1   = (const float*)d_in[11];
    const float* attn_W2   = (const float*)d_in[12];
    const float* attn_b2   = (const float*)d_in[13];
    const float* val_W1    = (const float*)d_in[14];
    const float* val_b1    = (const float*)d_in[15];
    const float* val_W2    = (const float*)d_in[16];
    const float* val_b2    = (const float*)d_in[17];
    const float* fallback  = (const float*)d_in[18];
    float* out = (float*)d_out;

    reset_flags<<<1, 1>>>();
    detect_valid<<<148, 1024>>>((const unsigned int*)validp, (B_TOTAL * KNB) / 4);
    prep_tables<<<148, 256>>>(attn_W1, attn_b1, val_W1, val_b1, val_W2,
                              res_table, ss_table, cont_W, cont_b);
    prep_fuse<<<148, 256>>>();

    fused_all<<<B_TOTAL / TILE_B, 256, SMEM_BYTES>>>(
        res_idx, ss_idx, dist, seq_sep, angles, validp,
        attn_W2, attn_b2, val_b2, fallback, out);
}